// round 10
// baseline (speedup 1.0000x reference)
#include <cuda_runtime.h>
#include <cstdint>

#define NUSERS 100000
#define NITEMS 200000
#define NNODES 300000
#define DIM 64
#define ROWSTRIDE 256            // LEVELS * DIM
#define NNZ_E 1200000
#define NHOPS 3
#define INV_MESS_KEEP 1.1111112f // fp32(1/0.9)

#define MASK_WORDS 600000        // NNODES*DIM/32 bits per hop
#define MASK_BLOCKS 75000        // 19.2M elements / 256 threads
#define SPMM_BLOCKS 37500        // NNODES*32 threads / 256

#define SCAN_BLK 1024
#define NBLK ((NNODES + SCAN_BLK - 1) / SCAN_BLK)   // 293

// Scratch (__device__ globals; no allocations allowed). ~28 MB total.
__device__ unsigned g_deg[NNODES];        // degree histogram, then scatter cursor
__device__ unsigned g_rowptr[NNODES + 1]; // CSR row pointers
__device__ unsigned g_bsum[NBLK];         // scan block sums
__device__ float4   g_ew3[NNZ_E];         // CSR-ordered {w_hop0, w_hop1, w_hop2, bitcast(col)}
__device__ unsigned g_mask[NHOPS * MASK_WORDS];  // message-dropout keep bits

// ---------------------------------------------------------------------------
// Threefry-2x32 (JAX partitionable mode) — validated bit-exact (rel_err 7e-8)
// ---------------------------------------------------------------------------
__host__ __device__ __forceinline__ uint32_t rotl32(uint32_t x, int r) {
#ifdef __CUDA_ARCH__
    return __funnelshift_l(x, x, r);
#else
    return (x << r) | (x >> (32 - r));
#endif
}

__host__ __device__ __forceinline__ void threefry2x32(
    uint32_t k0, uint32_t k1, uint32_t x0, uint32_t x1,
    uint32_t& o0, uint32_t& o1)
{
    uint32_t ks2 = k0 ^ k1 ^ 0x1BD11BDAu;
    x0 += k0; x1 += k1;
#define TF_R(r) { x0 += x1; x1 = rotl32(x1, r); x1 ^= x0; }
    TF_R(13) TF_R(15) TF_R(26) TF_R(6)
    x0 += k1;  x1 += ks2 + 1u;
    TF_R(17) TF_R(29) TF_R(16) TF_R(24)
    x0 += ks2; x1 += k0 + 2u;
    TF_R(13) TF_R(15) TF_R(26) TF_R(6)
    x0 += k0;  x1 += k1 + 3u;
    TF_R(17) TF_R(29) TF_R(16) TF_R(24)
    x0 += k1;  x1 += ks2 + 4u;
    TF_R(13) TF_R(15) TF_R(26) TF_R(6)
    x0 += ks2; x1 += k0 + 5u;
#undef TF_R
    o0 = x0; o1 = x1;
}

__device__ __forceinline__ uint32_t tf_bits(uint32_t k0, uint32_t k1, uint32_t i) {
    uint32_t a, b;
    threefry2x32(k0, k1, 0u, i, a, b);
    return a ^ b;
}

__device__ __forceinline__ float bits_to_u01(uint32_t bits) {
    return __uint_as_float((bits >> 9) | 0x3f800000u) - 1.0f;
}

// mask chunk: 256 consecutive elements starting at mb*256; one ballot/warp
__device__ __forceinline__ void mask_chunk(unsigned mb, uint32_t k0, uint32_t k1,
                                           unsigned* dst)
{
    unsigned j = mb * 256u + threadIdx.x;
    float u = bits_to_u01(tf_bits(k0, k1, j));
    unsigned bits = __ballot_sync(0xFFFFFFFFu, u < 0.9f);
    if ((threadIdx.x & 31u) == 0u) dst[j >> 5] = bits;
}

// ---------------------------------------------------------------------------
// CSR build: zero -> histogram -> 2-level exclusive scan
// ---------------------------------------------------------------------------
__global__ void __launch_bounds__(256)
k_zero()
{
    unsigned i = blockIdx.x * blockDim.x + threadIdx.x;
    if (i < NNODES) g_deg[i] = 0u;
}

__global__ void __launch_bounds__(256)
k_hist(const int* __restrict__ rows)
{
    unsigned e = blockIdx.x * blockDim.x + threadIdx.x;
    if (e >= NNZ_E) return;
    atomicAdd(&g_deg[rows[e]], 1u);
}

__global__ void __launch_bounds__(256)
k_scan1()
{
    __shared__ unsigned warp_sums[8];
    unsigned b = blockIdx.x;
    unsigned base = b * SCAN_BLK + threadIdx.x * 4u;
    unsigned v[4];
#pragma unroll
    for (int i = 0; i < 4; i++) {
        unsigned idx = base + i;
        v[i] = (idx < NNODES) ? g_deg[idx] : 0u;
    }
    unsigned tsum = v[0] + v[1] + v[2] + v[3];
    unsigned lane = threadIdx.x & 31u, wid = threadIdx.x >> 5;
    unsigned x = tsum;
#pragma unroll
    for (int o = 1; o < 32; o <<= 1) {
        unsigned y = __shfl_up_sync(0xFFFFFFFFu, x, o);
        if (lane >= (unsigned)o) x += y;
    }
    if (lane == 31) warp_sums[wid] = x;
    __syncthreads();
    if (wid == 0) {
        unsigned s = (lane < 8) ? warp_sums[lane] : 0u;
#pragma unroll
        for (int o = 1; o < 8; o <<= 1) {
            unsigned y = __shfl_up_sync(0xFFFFFFFFu, s, o);
            if (lane >= (unsigned)o) s += y;
        }
        if (lane < 8) warp_sums[lane] = s;
    }
    __syncthreads();
    unsigned warp_off = (wid > 0) ? warp_sums[wid - 1] : 0u;
    unsigned run = warp_off + (x - tsum);
#pragma unroll
    for (int i = 0; i < 4; i++) {
        unsigned idx = base + i;
        if (idx < NNODES) g_rowptr[idx] = run;
        run += v[i];
    }
    if (threadIdx.x == 255) g_bsum[b] = warp_sums[7];
}

__global__ void __launch_bounds__(512)
k_scan2()
{
    __shared__ unsigned sm[512];
    unsigned t = threadIdx.x;
    sm[t] = (t < NBLK) ? g_bsum[t] : 0u;
    __syncthreads();
#pragma unroll
    for (int o = 1; o < 512; o <<= 1) {
        unsigned y = (t >= (unsigned)o) ? sm[t - o] : 0u;
        __syncthreads();
        sm[t] += y;
        __syncthreads();
    }
    if (t < NBLK) g_bsum[t] = (t == 0) ? 0u : sm[t - 1];
}

__global__ void __launch_bounds__(256)
k_scan3()
{
    unsigned i = blockIdx.x * blockDim.x + threadIdx.x;
    if (i < NNODES) {
        g_rowptr[i] += g_bsum[i >> 10];
        g_deg[i] = 0u;                     // reuse as scatter cursor
    }
    if (i == 0) g_rowptr[NNODES] = NNZ_E;
}

// ---------------------------------------------------------------------------
// prep: heterogeneous blocks. 1-of-17 blocks: CSR scatter + all-hop edge RNG
// (memory/atomic-bound). 16-of-17 blocks: hop-0 message mask (ALU-bound).
// ---------------------------------------------------------------------------
#define PREP_GRID 80000
__global__ void __launch_bounds__(256)
k_prep(const int* __restrict__ rows, const int* __restrict__ cols,
       const float* __restrict__ vals,
       uint32_t ka0, uint32_t ka1, uint32_t kb0, uint32_t kb1,
       uint32_t kc0, uint32_t kc1, uint32_t km0, uint32_t km1)
{
    unsigned b = blockIdx.x;
    if (b % 17u == 0u) {
        unsigned e = (b / 17u) * 256u + threadIdx.x;
        if (e >= NNZ_E) return;
        int r = rows[e];
        float v2 = vals[e] * 2.0f;
        float u0 = bits_to_u01(tf_bits(ka0, ka1, e));
        float u1 = bits_to_u01(tf_bits(kb0, kb1, e));
        float u2 = bits_to_u01(tf_bits(kc0, kc1, e));
        float4 ew;
        ew.x = (u0 >= 0.5f) ? v2 : 0.0f;
        ew.y = (u1 >= 0.5f) ? v2 : 0.0f;
        ew.z = (u2 >= 0.5f) ? v2 : 0.0f;
        ew.w = __int_as_float(cols[e]);
        unsigned pos = g_rowptr[r] + atomicAdd(&g_deg[r], 1u);
        g_ew3[pos] = ew;
    } else {
        unsigned mb = b - b / 17u - 1u;
        if (mb < MASK_BLOCKS) mask_chunk(mb, km0, km1, g_mask);
    }
}

// ---------------------------------------------------------------------------
// hop kernel: heterogeneous blocks. 1-of-3: SpMM (RNG-free, memory-bound,
// reads precomputed mask for HOP). 2-of-3: compute mask for HOP+1 (ALU).
// HOP==2 launches with SPMM_BLOCKS only (no next mask).
// ---------------------------------------------------------------------------
template <int HOP>
__global__ void __launch_bounds__(256)
k_hop(const float* __restrict__ ue, const float* __restrict__ ie,
      float* __restrict__ out, uint32_t kn0, uint32_t kn1)
{
    unsigned b = blockIdx.x;
    if (HOP < 2) {
        if (b % 3u != 0u) {
            unsigned mb = (b / 3u) * 2u + (b % 3u) - 1u;   // exactly [0, 75000)
            mask_chunk(mb, kn0, kn1, g_mask + (HOP + 1) * MASK_WORDS);
            return;
        }
        b /= 3u;
    }

    unsigned r = b * 8u + (threadIdx.x >> 5);   // row (8 warps/block)
    if (r >= NNODES) return;
    unsigned lane = threadIdx.x & 31u;

    // issue all front loads immediately (independent, scoreboarded)
    unsigned start = __ldg(&g_rowptr[r]);
    unsigned end   = __ldg(&g_rowptr[r + 1]);
    unsigned mword = __ldg(&g_mask[HOP * MASK_WORDS + r * 2u + (lane >> 4)]);

    unsigned p0 = 2u * (lane & 15u);
    float keep0 = ((mword >> p0) & 1u)        ? INV_MESS_KEEP : 0.0f;
    float keep1 = ((mword >> (p0 + 1u)) & 1u) ? INV_MESS_KEEP : 0.0f;

    float2 acc = make_float2(0.f, 0.f);
    const float* src_base = out + (size_t)HOP * DIM;   // when HOP>0

    auto wsel = [](const float4& e) {
        return (HOP == 0) ? e.x : (HOP == 1) ? e.y : e.z;
    };
    auto srow_of = [&](int c) -> const float* {
        if (HOP == 0)
            return (c < NUSERS) ? (ue + (size_t)c * DIM)
                                : (ie + (size_t)(c - NUSERS) * DIM);
        return src_base + (size_t)c * ROWSTRIDE;
    };

    const float4 z4 = make_float4(0.f, 0.f, 0.f, 0.f);
    for (unsigned p = start; p < end; p += 4u) {
        float4 e0 = g_ew3[p];
        float4 e1 = (p + 1u < end) ? g_ew3[p + 1u] : z4;
        float4 e2 = (p + 2u < end) ? g_ew3[p + 2u] : z4;
        float4 e3 = (p + 3u < end) ? g_ew3[p + 3u] : z4;
        float w0 = wsel(e0), w1 = wsel(e1), w2 = wsel(e2), w3 = wsel(e3);
        float2 s0 = make_float2(0.f, 0.f), s1 = s0, s2 = s0, s3 = s0;
        if (w0 != 0.f) s0 = *reinterpret_cast<const float2*>(srow_of(__float_as_int(e0.w)) + lane * 2u);
        if (w1 != 0.f) s1 = *reinterpret_cast<const float2*>(srow_of(__float_as_int(e1.w)) + lane * 2u);
        if (w2 != 0.f) s2 = *reinterpret_cast<const float2*>(srow_of(__float_as_int(e2.w)) + lane * 2u);
        if (w3 != 0.f) s3 = *reinterpret_cast<const float2*>(srow_of(__float_as_int(e3.w)) + lane * 2u);
        acc.x += w0 * s0.x + w1 * s1.x + w2 * s2.x + w3 * s3.x;
        acc.y += w0 * s0.y + w1 * s1.y + w2 * s2.y + w3 * s3.y;
    }

    float2 res;
    res.x = acc.x * keep0;
    res.y = acc.y * keep1;

    float* orow = out + (size_t)r * ROWSTRIDE;
    *reinterpret_cast<float2*>(orow + (size_t)(HOP + 1) * DIM + lane * 2u) = res;

    if (HOP == 0) {
        const float* erow = (r < NUSERS) ? (ue + (size_t)r * DIM)
                                         : (ie + (size_t)(r - NUSERS) * DIM);
        float2 e0 = *reinterpret_cast<const float2*>(erow + lane * 2u);
        *reinterpret_cast<float2*>(orow + lane * 2u) = e0;
    }
}

// ---------------------------------------------------------------------------
// Launch
// ---------------------------------------------------------------------------
extern "C" void kernel_launch(void* const* d_in, const int* in_sizes, int n_in,
                              void* d_out, int out_size)
{
    const float* ue = nullptr; const float* ie = nullptr;
    const float* vals = nullptr; const int* rows = nullptr; const int* cols = nullptr;
    int nnz_seen = 0;
    for (int i = 0; i < n_in; i++) {
        if (in_sizes[i] == NUSERS * DIM)      ue = (const float*)d_in[i];
        else if (in_sizes[i] == NITEMS * DIM) ie = (const float*)d_in[i];
        else if (in_sizes[i] == NNZ_E) {
            if (nnz_seen == 0)      vals = (const float*)d_in[i];
            else if (nnz_seen == 1) rows = (const int*)d_in[i];
            else                    cols = (const int*)d_in[i];
            nnz_seen++;
        }
    }
    float* out = (float*)d_out;

    // JAX key derivation (validated): base=(0,42); hk=cipher(base,(0,hop));
    // ke=cipher(hk,(0,0)), km=cipher(hk,(0,1))
    uint32_t ke0[NHOPS], ke1[NHOPS], km0[NHOPS], km1[NHOPS];
    for (int h = 0; h < NHOPS; h++) {
        uint32_t h0, h1;
        threefry2x32(0u, 42u, 0u, (uint32_t)h, h0, h1);
        threefry2x32(h0, h1, 0u, 0u, ke0[h], ke1[h]);
        threefry2x32(h0, h1, 0u, 1u, km0[h], km1[h]);
    }

    const int TB = 256;
    unsigned gb_node = (NNODES + TB - 1) / TB;
    unsigned gb_edge = (NNZ_E + TB - 1) / TB;

    k_zero<<<gb_node, TB>>>();
    k_hist<<<gb_edge, TB>>>(rows);
    k_scan1<<<NBLK, TB>>>();
    k_scan2<<<1, 512>>>();
    k_scan3<<<gb_node, TB>>>();
    k_prep<<<PREP_GRID, TB>>>(rows, cols, vals,
                              ke0[0], ke1[0], ke0[1], ke1[1], ke0[2], ke1[2],
                              km0[0], km1[0]);

    k_hop<0><<<SPMM_BLOCKS * 3, TB>>>(ue, ie, out, km0[1], km1[1]);
    k_hop<1><<<SPMM_BLOCKS * 3, TB>>>(ue, ie, out, km0[2], km1[2]);
    k_hop<2><<<SPMM_BLOCKS, TB>>>(ue, ie, out, 0u, 0u);
}

// round 11
// speedup vs baseline: 1.3383x; 1.3383x over previous
#include <cuda_runtime.h>
#include <cstdint>

#define NUSERS 100000
#define NITEMS 200000
#define NNODES 300000
#define DIM 64
#define ROWSTRIDE 256            // LEVELS * DIM
#define NNZ_E 1200000
#define NHOPS 3
#define INV_MESS_KEEP 1.1111112f // fp32(1/0.9)

// integer threshold: u < 0.9f  <=>  (bits>>9) <= MESS_THR  (exact, see notes)
#define MESS_THR 7549746u

#define SCAN_BLK 1024
#define NBLK ((NNODES + SCAN_BLK - 1) / SCAN_BLK)   // 293

// Scratch (__device__ globals; no allocations allowed). ~21 MB total.
__device__ unsigned g_deg[NNODES];        // degree histogram, then scatter cursor
__device__ unsigned g_rowptr[NNODES + 1]; // CSR row pointers
__device__ unsigned g_bsum[NBLK];         // scan block sums
__device__ float4   g_ew3[NNZ_E];         // CSR-ordered {w_hop0, w_hop1, w_hop2, bitcast(col)}

// ---------------------------------------------------------------------------
// Threefry-2x32 (JAX partitionable mode) — validated bit-exact (rel_err 7e-8)
// ---------------------------------------------------------------------------
__host__ __device__ __forceinline__ uint32_t rotl32(uint32_t x, int r) {
#ifdef __CUDA_ARCH__
    return __funnelshift_l(x, x, r);
#else
    return (x << r) | (x >> (32 - r));
#endif
}

__host__ __device__ __forceinline__ void threefry2x32(
    uint32_t k0, uint32_t k1, uint32_t x0, uint32_t x1,
    uint32_t& o0, uint32_t& o1)
{
    uint32_t ks2 = k0 ^ k1 ^ 0x1BD11BDAu;
    x0 += k0; x1 += k1;
#define TF_R(r) { x0 += x1; x1 = rotl32(x1, r); x1 ^= x0; }
    TF_R(13) TF_R(15) TF_R(26) TF_R(6)
    x0 += k1;  x1 += ks2 + 1u;
    TF_R(17) TF_R(29) TF_R(16) TF_R(24)
    x0 += ks2; x1 += k0 + 2u;
    TF_R(13) TF_R(15) TF_R(26) TF_R(6)
    x0 += k0;  x1 += k1 + 3u;
    TF_R(17) TF_R(29) TF_R(16) TF_R(24)
    x0 += k1;  x1 += ks2 + 4u;
    TF_R(13) TF_R(15) TF_R(26) TF_R(6)
    x0 += ks2; x1 += k0 + 5u;
#undef TF_R
    o0 = x0; o1 = x1;
}

__device__ __forceinline__ uint32_t tf_bits(uint32_t k0, uint32_t k1, uint32_t i) {
    uint32_t a, b;
    threefry2x32(k0, k1, 0u, i, a, b);
    return a ^ b;
}

// ---------------------------------------------------------------------------
// CSR build: zero -> histogram -> 2-level exclusive scan -> scatter(+edge RNG)
// ---------------------------------------------------------------------------
__global__ void __launch_bounds__(256)
k_zero()
{
    unsigned i = blockIdx.x * blockDim.x + threadIdx.x;
    if (i < NNODES) g_deg[i] = 0u;
}

__global__ void __launch_bounds__(256)
k_hist(const int* __restrict__ rows)
{
    unsigned e = blockIdx.x * blockDim.x + threadIdx.x;
    if (e >= NNZ_E) return;
    atomicAdd(&g_deg[rows[e]], 1u);
}

// per-block exclusive scan over 1024 elems (256 threads x 4)
__global__ void __launch_bounds__(256)
k_scan1()
{
    __shared__ unsigned warp_sums[8];
    unsigned b = blockIdx.x;
    unsigned base = b * SCAN_BLK + threadIdx.x * 4u;
    unsigned v[4];
#pragma unroll
    for (int i = 0; i < 4; i++) {
        unsigned idx = base + i;
        v[i] = (idx < NNODES) ? g_deg[idx] : 0u;
    }
    unsigned tsum = v[0] + v[1] + v[2] + v[3];
    unsigned lane = threadIdx.x & 31u, wid = threadIdx.x >> 5;
    unsigned x = tsum;
#pragma unroll
    for (int o = 1; o < 32; o <<= 1) {
        unsigned y = __shfl_up_sync(0xFFFFFFFFu, x, o);
        if (lane >= (unsigned)o) x += y;
    }
    if (lane == 31) warp_sums[wid] = x;
    __syncthreads();
    if (wid == 0) {
        unsigned s = (lane < 8) ? warp_sums[lane] : 0u;
#pragma unroll
        for (int o = 1; o < 8; o <<= 1) {
            unsigned y = __shfl_up_sync(0xFFFFFFFFu, s, o);
            if (lane >= (unsigned)o) s += y;
        }
        if (lane < 8) warp_sums[lane] = s;
    }
    __syncthreads();
    unsigned warp_off = (wid > 0) ? warp_sums[wid - 1] : 0u;
    unsigned run = warp_off + (x - tsum);
#pragma unroll
    for (int i = 0; i < 4; i++) {
        unsigned idx = base + i;
        if (idx < NNODES) g_rowptr[idx] = run;
        run += v[i];
    }
    if (threadIdx.x == 255) g_bsum[b] = warp_sums[7];
}

// single-block exclusive scan of block sums (NBLK = 293 <= 512)
__global__ void __launch_bounds__(512)
k_scan2()
{
    __shared__ unsigned sm[512];
    unsigned t = threadIdx.x;
    sm[t] = (t < NBLK) ? g_bsum[t] : 0u;
    __syncthreads();
#pragma unroll
    for (int o = 1; o < 512; o <<= 1) {
        unsigned y = (t >= (unsigned)o) ? sm[t - o] : 0u;
        __syncthreads();
        sm[t] += y;
        __syncthreads();
    }
    if (t < NBLK) g_bsum[t] = (t == 0) ? 0u : sm[t - 1];
}

__global__ void __launch_bounds__(256)
k_scan3()
{
    unsigned i = blockIdx.x * blockDim.x + threadIdx.x;
    if (i < NNODES) {
        g_rowptr[i] += g_bsum[i >> 10];
        g_deg[i] = 0u;                     // reuse as scatter cursor
    }
    if (i == 0) g_rowptr[NNODES] = NNZ_E;
}

// scatter + ALL-HOP edge dropout RNG; writes CSR-ordered {w0,w1,w2,col}
// edge keep: u >= 0.5f  <=>  top bit of bits set (exact)
__global__ void __launch_bounds__(256)
k_scatter(const int* __restrict__ rows, const int* __restrict__ cols,
          const float* __restrict__ vals,
          uint32_t ka0, uint32_t ka1, uint32_t kb0, uint32_t kb1,
          uint32_t kc0, uint32_t kc1)
{
    unsigned e = blockIdx.x * blockDim.x + threadIdx.x;
    if (e >= NNZ_E) return;
    int r = rows[e];
    float v2 = vals[e] * 2.0f;
    uint32_t b0 = tf_bits(ka0, ka1, e);
    uint32_t b1 = tf_bits(kb0, kb1, e);
    uint32_t b2 = tf_bits(kc0, kc1, e);
    float4 ew;
    ew.x = (b0 & 0x80000000u) ? v2 : 0.0f;
    ew.y = (b1 & 0x80000000u) ? v2 : 0.0f;
    ew.z = (b2 & 0x80000000u) ? v2 : 0.0f;
    ew.w = __int_as_float(cols[e]);
    unsigned pos = g_rowptr[r] + atomicAdd(&g_deg[r], 1u);
    g_ew3[pos] = ew;
}

// ---------------------------------------------------------------------------
// Fused SpMM + message dropout. ONE warp per row, float2 per lane.
// Message-dropout ciphers computed FIRST (hoisted above the gather loop) so
// their ALU work issues under the rowptr/edge/gather load latency.
// Keep test is a pure integer compare: (bits>>9) <= MESS_THR  <=>  u < 0.9f.
// ---------------------------------------------------------------------------
template <int HOP>
__global__ void __launch_bounds__(256)
k_spmm_fused(const float* __restrict__ ue, const float* __restrict__ ie,
             float* __restrict__ out, uint32_t km0, uint32_t km1)
{
    unsigned r = (blockIdx.x * blockDim.x + threadIdx.x) >> 5;  // row
    if (r >= NNODES) return;
    unsigned lane = threadIdx.x & 31u;

    // issue rowptr loads immediately (scoreboarded)
    unsigned start = __ldg(&g_rowptr[r]);
    unsigned end   = __ldg(&g_rowptr[r + 1]);

    // --- hoisted message-dropout RNG: pure ALU, independent of all loads ---
    unsigned j = r * 64u + lane * 2u;
    uint32_t a0, b0, a1, b1;
    threefry2x32(km0, km1, 0u, j,      a0, b0);
    threefry2x32(km0, km1, 0u, j + 1u, a1, b1);
    float keep0 = (((a0 ^ b0) >> 9) <= MESS_THR) ? INV_MESS_KEEP : 0.0f;
    float keep1 = (((a1 ^ b1) >> 9) <= MESS_THR) ? INV_MESS_KEEP : 0.0f;

    float2 acc = make_float2(0.f, 0.f);
    const float* src_base = out + (size_t)HOP * DIM;   // when HOP>0

    auto wsel = [](const float4& e) {
        return (HOP == 0) ? e.x : (HOP == 1) ? e.y : e.z;
    };
    auto srow_of = [&](int c) -> const float* {
        if (HOP == 0)
            return (c < NUSERS) ? (ue + (size_t)c * DIM)
                                : (ie + (size_t)(c - NUSERS) * DIM);
        return src_base + (size_t)c * ROWSTRIDE;
    };

    const float4 z4 = make_float4(0.f, 0.f, 0.f, 0.f);
    for (unsigned p = start; p < end; p += 4u) {
        // 4 independent broadcast loads (predicated; all lanes same address)
        float4 e0 = g_ew3[p];
        float4 e1 = (p + 1u < end) ? g_ew3[p + 1u] : z4;
        float4 e2 = (p + 2u < end) ? g_ew3[p + 2u] : z4;
        float4 e3 = (p + 3u < end) ? g_ew3[p + 3u] : z4;
        float w0 = wsel(e0), w1 = wsel(e1), w2 = wsel(e2), w3 = wsel(e3);
        // 4 independent gathers
        float2 s0 = make_float2(0.f, 0.f), s1 = s0, s2 = s0, s3 = s0;
        if (w0 != 0.f) s0 = *reinterpret_cast<const float2*>(srow_of(__float_as_int(e0.w)) + lane * 2u);
        if (w1 != 0.f) s1 = *reinterpret_cast<const float2*>(srow_of(__float_as_int(e1.w)) + lane * 2u);
        if (w2 != 0.f) s2 = *reinterpret_cast<const float2*>(srow_of(__float_as_int(e2.w)) + lane * 2u);
        if (w3 != 0.f) s3 = *reinterpret_cast<const float2*>(srow_of(__float_as_int(e3.w)) + lane * 2u);
        acc.x += w0 * s0.x + w1 * s1.x + w2 * s2.x + w3 * s3.x;
        acc.y += w0 * s0.y + w1 * s1.y + w2 * s2.y + w3 * s3.y;
    }

    // tiny epilogue: apply precomputed keep factors and store
    float2 res;
    res.x = acc.x * keep0;
    res.y = acc.y * keep1;

    float* orow = out + (size_t)r * ROWSTRIDE;
    *reinterpret_cast<float2*>(orow + (size_t)(HOP + 1) * DIM + lane * 2u) = res;

    if (HOP == 0) {
        // emit level-0 copy (row r of concat(ue, ie))
        const float* erow = (r < NUSERS) ? (ue + (size_t)r * DIM)
                                         : (ie + (size_t)(r - NUSERS) * DIM);
        float2 e0 = *reinterpret_cast<const float2*>(erow + lane * 2u);
        *reinterpret_cast<float2*>(orow + lane * 2u) = e0;
    }
}

// ---------------------------------------------------------------------------
// Launch
// ---------------------------------------------------------------------------
extern "C" void kernel_launch(void* const* d_in, const int* in_sizes, int n_in,
                              void* d_out, int out_size)
{
    const float* ue = nullptr; const float* ie = nullptr;
    const float* vals = nullptr; const int* rows = nullptr; const int* cols = nullptr;
    int nnz_seen = 0;
    for (int i = 0; i < n_in; i++) {
        if (in_sizes[i] == NUSERS * DIM)      ue = (const float*)d_in[i];
        else if (in_sizes[i] == NITEMS * DIM) ie = (const float*)d_in[i];
        else if (in_sizes[i] == NNZ_E) {
            if (nnz_seen == 0)      vals = (const float*)d_in[i];
            else if (nnz_seen == 1) rows = (const int*)d_in[i];
            else                    cols = (const int*)d_in[i];
            nnz_seen++;
        }
    }
    float* out = (float*)d_out;

    // JAX key derivation (validated): base=(0,42); hk=cipher(base,(0,hop));
    // ke=cipher(hk,(0,0)), km=cipher(hk,(0,1))
    uint32_t ke0[NHOPS], ke1[NHOPS], km0[NHOPS], km1[NHOPS];
    for (int h = 0; h < NHOPS; h++) {
        uint32_t h0, h1;
        threefry2x32(0u, 42u, 0u, (uint32_t)h, h0, h1);
        threefry2x32(h0, h1, 0u, 0u, ke0[h], ke1[h]);
        threefry2x32(h0, h1, 0u, 1u, km0[h], km1[h]);
    }

    const int TB = 256;
    unsigned gb_node = (NNODES + TB - 1) / TB;
    unsigned gb_edge = (NNZ_E + TB - 1) / TB;
    unsigned gb_fuse = ((unsigned)NNODES * 32u + TB - 1) / TB;  // 1 warp/row

    k_zero<<<gb_node, TB>>>();
    k_hist<<<gb_edge, TB>>>(rows);
    k_scan1<<<NBLK, TB>>>();
    k_scan2<<<1, 512>>>();
    k_scan3<<<gb_node, TB>>>();
    k_scatter<<<gb_edge, TB>>>(rows, cols, vals,
                               ke0[0], ke1[0], ke0[1], ke1[1], ke0[2], ke1[2]);

    k_spmm_fused<0><<<gb_fuse, TB>>>(ue, ie, out, km0[0], km1[0]);
    k_spmm_fused<1><<<gb_fuse, TB>>>(ue, ie, out, km0[1], km1[1]);
    k_spmm_fused<2><<<gb_fuse, TB>>>(ue, ie, out, km0[2], km1[2]);
}

// round 12
// speedup vs baseline: 1.3462x; 1.0059x over previous
#include <cuda_runtime.h>
#include <cstdint>

#define NUSERS 100000
#define NITEMS 200000
#define NNODES 300000
#define DIM 64
#define ROWSTRIDE 256            // LEVELS * DIM
#define NNZ_E 1200000
#define NHOPS 3
#define INV_MESS_KEEP 1.1111112f // fp32(1/0.9)

#define SCAN_BLK 1024
#define NBLK ((NNODES + SCAN_BLK - 1) / SCAN_BLK)   // 293

// Scratch (__device__ globals; no allocations allowed). ~21 MB total.
__device__ unsigned g_deg[NNODES];        // degree histogram, then scatter cursor
__device__ unsigned g_rowptr[NNODES + 1]; // CSR row pointers
__device__ unsigned g_bsum[NBLK];         // scan block sums
__device__ float4   g_ew3[NNZ_E];         // CSR-ordered {w_hop0, w_hop1, w_hop2, bitcast(col)}

// ---------------------------------------------------------------------------
// Threefry-2x32 (JAX partitionable mode) — validated bit-exact (rel_err 7e-8)
// ---------------------------------------------------------------------------
__host__ __device__ __forceinline__ uint32_t rotl32(uint32_t x, int r) {
#ifdef __CUDA_ARCH__
    return __funnelshift_l(x, x, r);
#else
    return (x << r) | (x >> (32 - r));
#endif
}

__host__ __device__ __forceinline__ void threefry2x32(
    uint32_t k0, uint32_t k1, uint32_t x0, uint32_t x1,
    uint32_t& o0, uint32_t& o1)
{
    uint32_t ks2 = k0 ^ k1 ^ 0x1BD11BDAu;
    x0 += k0; x1 += k1;
#define TF_R(r) { x0 += x1; x1 = rotl32(x1, r); x1 ^= x0; }
    TF_R(13) TF_R(15) TF_R(26) TF_R(6)
    x0 += k1;  x1 += ks2 + 1u;
    TF_R(17) TF_R(29) TF_R(16) TF_R(24)
    x0 += ks2; x1 += k0 + 2u;
    TF_R(13) TF_R(15) TF_R(26) TF_R(6)
    x0 += k0;  x1 += k1 + 3u;
    TF_R(17) TF_R(29) TF_R(16) TF_R(24)
    x0 += k1;  x1 += ks2 + 4u;
    TF_R(13) TF_R(15) TF_R(26) TF_R(6)
    x0 += ks2; x1 += k0 + 5u;
#undef TF_R
    o0 = x0; o1 = x1;
}

// Pipe-balanced variant: every add is a*ONE+b with ONE an opaque runtime 1,
// forcing IMAD on the (idle) fma pipe; SHF/LOP3 stay on the alu pipe.
// Bit-identical results since ONE == 1.
__device__ __forceinline__ uint32_t madd(uint32_t a, uint32_t one, uint32_t b) {
    return a * one + b;   // -> IMAD (fma pipe)
}

__device__ __forceinline__ void threefry2x32_bal(
    uint32_t k0, uint32_t k1, uint32_t x0, uint32_t x1, uint32_t one,
    uint32_t& o0, uint32_t& o1)
{
    uint32_t ks2 = k0 ^ k1 ^ 0x1BD11BDAu;
    x0 = madd(x0, one, k0); x1 = madd(x1, one, k1);
#define TF_RB(r) { x0 = madd(x0, one, x1); x1 = rotl32(x1, r); x1 ^= x0; }
    TF_RB(13) TF_RB(15) TF_RB(26) TF_RB(6)
    x0 = madd(x0, one, k1);  x1 = madd(x1, one, ks2 + 1u);
    TF_RB(17) TF_RB(29) TF_RB(16) TF_RB(24)
    x0 = madd(x0, one, ks2); x1 = madd(x1, one, k0 + 2u);
    TF_RB(13) TF_RB(15) TF_RB(26) TF_RB(6)
    TF_RB(17) TF_RB(29) TF_RB(16) TF_RB(24)
    // note: the two skipped injections above must not be skipped — keep exact
#undef TF_RB
    o0 = x0; o1 = x1;
}

// (Correct full-schedule balanced cipher; the abbreviated one above is unused.)
__device__ __forceinline__ void threefry2x32_bal_full(
    uint32_t k0, uint32_t k1, uint32_t x0, uint32_t x1, uint32_t one,
    uint32_t& o0, uint32_t& o1)
{
    uint32_t ks2 = k0 ^ k1 ^ 0x1BD11BDAu;
    x0 = madd(x0, one, k0); x1 = madd(x1, one, k1);
#define TF_RB(r) { x0 = madd(x0, one, x1); x1 = rotl32(x1, r); x1 ^= x0; }
    TF_RB(13) TF_RB(15) TF_RB(26) TF_RB(6)
    x0 = madd(x0, one, k1);  x1 = madd(x1, one, ks2 + 1u);
    TF_RB(17) TF_RB(29) TF_RB(16) TF_RB(24)
    x0 = madd(x0, one, ks2); x1 = madd(x1, one, k0 + 2u);
    TF_RB(13) TF_RB(15) TF_RB(26) TF_RB(6)
    x0 = madd(x0, one, k0);  x1 = madd(x1, one, k1 + 3u);
    TF_RB(17) TF_RB(29) TF_RB(16) TF_RB(24)
    x0 = madd(x0, one, k1);  x1 = madd(x1, one, ks2 + 4u);
    TF_RB(13) TF_RB(15) TF_RB(26) TF_RB(6)
    x0 = madd(x0, one, ks2); x1 = madd(x1, one, k0 + 5u);
#undef TF_RB
    o0 = x0; o1 = x1;
}

__device__ __forceinline__ uint32_t tf_bits(uint32_t k0, uint32_t k1, uint32_t i) {
    uint32_t a, b;
    threefry2x32(k0, k1, 0u, i, a, b);
    return a ^ b;
}

__device__ __forceinline__ float bits_to_u01(uint32_t bits) {
    return __uint_as_float((bits >> 9) | 0x3f800000u) - 1.0f;
}

// ---------------------------------------------------------------------------
// CSR build: zero -> histogram -> 2-level exclusive scan -> scatter(+edge RNG)
// ---------------------------------------------------------------------------
__global__ void __launch_bounds__(256)
k_zero()
{
    unsigned i = blockIdx.x * blockDim.x + threadIdx.x;
    if (i < NNODES) g_deg[i] = 0u;
}

__global__ void __launch_bounds__(256)
k_hist(const int* __restrict__ rows)
{
    unsigned e = blockIdx.x * blockDim.x + threadIdx.x;
    if (e >= NNZ_E) return;
    atomicAdd(&g_deg[rows[e]], 1u);
}

// per-block exclusive scan over 1024 elems (256 threads x 4)
__global__ void __launch_bounds__(256)
k_scan1()
{
    __shared__ unsigned warp_sums[8];
    unsigned b = blockIdx.x;
    unsigned base = b * SCAN_BLK + threadIdx.x * 4u;
    unsigned v[4];
#pragma unroll
    for (int i = 0; i < 4; i++) {
        unsigned idx = base + i;
        v[i] = (idx < NNODES) ? g_deg[idx] : 0u;
    }
    unsigned tsum = v[0] + v[1] + v[2] + v[3];
    unsigned lane = threadIdx.x & 31u, wid = threadIdx.x >> 5;
    unsigned x = tsum;
#pragma unroll
    for (int o = 1; o < 32; o <<= 1) {
        unsigned y = __shfl_up_sync(0xFFFFFFFFu, x, o);
        if (lane >= (unsigned)o) x += y;
    }
    if (lane == 31) warp_sums[wid] = x;
    __syncthreads();
    if (wid == 0) {
        unsigned s = (lane < 8) ? warp_sums[lane] : 0u;
#pragma unroll
        for (int o = 1; o < 8; o <<= 1) {
            unsigned y = __shfl_up_sync(0xFFFFFFFFu, s, o);
            if (lane >= (unsigned)o) s += y;
        }
        if (lane < 8) warp_sums[lane] = s;
    }
    __syncthreads();
    unsigned warp_off = (wid > 0) ? warp_sums[wid - 1] : 0u;
    unsigned run = warp_off + (x - tsum);
#pragma unroll
    for (int i = 0; i < 4; i++) {
        unsigned idx = base + i;
        if (idx < NNODES) g_rowptr[idx] = run;
        run += v[i];
    }
    if (threadIdx.x == 255) g_bsum[b] = warp_sums[7];
}

// single-block exclusive scan of block sums (NBLK = 293 <= 512)
__global__ void __launch_bounds__(512)
k_scan2()
{
    __shared__ unsigned sm[512];
    unsigned t = threadIdx.x;
    sm[t] = (t < NBLK) ? g_bsum[t] : 0u;
    __syncthreads();
#pragma unroll
    for (int o = 1; o < 512; o <<= 1) {
        unsigned y = (t >= (unsigned)o) ? sm[t - o] : 0u;
        __syncthreads();
        sm[t] += y;
        __syncthreads();
    }
    if (t < NBLK) g_bsum[t] = (t == 0) ? 0u : sm[t - 1];
}

__global__ void __launch_bounds__(256)
k_scan3()
{
    unsigned i = blockIdx.x * blockDim.x + threadIdx.x;
    if (i < NNODES) {
        g_rowptr[i] += g_bsum[i >> 10];
        g_deg[i] = 0u;                     // reuse as scatter cursor
    }
    if (i == 0) g_rowptr[NNODES] = NNZ_E;
}

// scatter + ALL-HOP edge dropout RNG; writes CSR-ordered {w0,w1,w2,col}
// edge keep: u >= 0.5f  <=>  top bit of bits set (exact)
__global__ void __launch_bounds__(256)
k_scatter(const int* __restrict__ rows, const int* __restrict__ cols,
          const float* __restrict__ vals,
          uint32_t ka0, uint32_t ka1, uint32_t kb0, uint32_t kb1,
          uint32_t kc0, uint32_t kc1)
{
    unsigned e = blockIdx.x * blockDim.x + threadIdx.x;
    if (e >= NNZ_E) return;
    int r = rows[e];
    float v2 = vals[e] * 2.0f;
    uint32_t b0 = tf_bits(ka0, ka1, e);
    uint32_t b1 = tf_bits(kb0, kb1, e);
    uint32_t b2 = tf_bits(kc0, kc1, e);
    float4 ew;
    ew.x = (b0 & 0x80000000u) ? v2 : 0.0f;
    ew.y = (b1 & 0x80000000u) ? v2 : 0.0f;
    ew.z = (b2 & 0x80000000u) ? v2 : 0.0f;
    ew.w = __int_as_float(cols[e]);
    unsigned pos = g_rowptr[r] + atomicAdd(&g_deg[r], 1u);
    g_ew3[pos] = ew;
}

// ---------------------------------------------------------------------------
// Fused SpMM + message dropout. ONE warp per row, float2 per lane.
// Hoisted RNG uses the IMAD-balanced cipher (adds on fma pipe); keep test is
// the float compare (FADD/FSETP, fp pipe) to stay off the saturated alu pipe.
// ---------------------------------------------------------------------------
template <int HOP>
__global__ void __launch_bounds__(256)
k_spmm_fused(const float* __restrict__ ue, const float* __restrict__ ie,
             float* __restrict__ out, uint32_t km0, uint32_t km1, uint32_t one)
{
    unsigned r = (blockIdx.x * blockDim.x + threadIdx.x) >> 5;  // row
    if (r >= NNODES) return;
    unsigned lane = threadIdx.x & 31u;

    // issue rowptr loads immediately (scoreboarded)
    unsigned start = __ldg(&g_rowptr[r]);
    unsigned end   = __ldg(&g_rowptr[r + 1]);

    // --- hoisted message-dropout RNG (pipe-balanced, independent of loads) ---
    unsigned j = r * 64u + lane * 2u;
    uint32_t a0, b0, a1, b1;
    threefry2x32_bal_full(km0, km1, 0u, j,      one, a0, b0);
    threefry2x32_bal_full(km0, km1, 0u, j + 1u, one, a1, b1);
    float u0 = bits_to_u01(a0 ^ b0);
    float u1 = bits_to_u01(a1 ^ b1);
    float keep0 = (u0 < 0.9f) ? INV_MESS_KEEP : 0.0f;
    float keep1 = (u1 < 0.9f) ? INV_MESS_KEEP : 0.0f;

    float2 acc = make_float2(0.f, 0.f);
    const float* src_base = out + (size_t)HOP * DIM;   // when HOP>0

    auto wsel = [](const float4& e) {
        return (HOP == 0) ? e.x : (HOP == 1) ? e.y : e.z;
    };
    auto srow_of = [&](int c) -> const float* {
        if (HOP == 0)
            return (c < NUSERS) ? (ue + (size_t)c * DIM)
                                : (ie + (size_t)(c - NUSERS) * DIM);
        return src_base + (size_t)c * ROWSTRIDE;
    };

    const float4 z4 = make_float4(0.f, 0.f, 0.f, 0.f);
    for (unsigned p = start; p < end; p += 4u) {
        // 4 independent broadcast loads (predicated; all lanes same address)
        float4 e0 = g_ew3[p];
        float4 e1 = (p + 1u < end) ? g_ew3[p + 1u] : z4;
        float4 e2 = (p + 2u < end) ? g_ew3[p + 2u] : z4;
        float4 e3 = (p + 3u < end) ? g_ew3[p + 3u] : z4;
        float w0 = wsel(e0), w1 = wsel(e1), w2 = wsel(e2), w3 = wsel(e3);
        // 4 independent gathers
        float2 s0 = make_float2(0.f, 0.f), s1 = s0, s2 = s0, s3 = s0;
        if (w0 != 0.f) s0 = *reinterpret_cast<const float2*>(srow_of(__float_as_int(e0.w)) + lane * 2u);
        if (w1 != 0.f) s1 = *reinterpret_cast<const float2*>(srow_of(__float_as_int(e1.w)) + lane * 2u);
        if (w2 != 0.f) s2 = *reinterpret_cast<const float2*>(srow_of(__float_as_int(e2.w)) + lane * 2u);
        if (w3 != 0.f) s3 = *reinterpret_cast<const float2*>(srow_of(__float_as_int(e3.w)) + lane * 2u);
        acc.x += w0 * s0.x + w1 * s1.x + w2 * s2.x + w3 * s3.x;
        acc.y += w0 * s0.y + w1 * s1.y + w2 * s2.y + w3 * s3.y;
    }

    // tiny epilogue: apply precomputed keep factors and store
    float2 res;
    res.x = acc.x * keep0;
    res.y = acc.y * keep1;

    float* orow = out + (size_t)r * ROWSTRIDE;
    *reinterpret_cast<float2*>(orow + (size_t)(HOP + 1) * DIM + lane * 2u) = res;

    if (HOP == 0) {
        // emit level-0 copy (row r of concat(ue, ie))
        const float* erow = (r < NUSERS) ? (ue + (size_t)r * DIM)
                                         : (ie + (size_t)(r - NUSERS) * DIM);
        float2 e0 = *reinterpret_cast<const float2*>(erow + lane * 2u);
        *reinterpret_cast<float2*>(orow + lane * 2u) = e0;
    }
}

// ---------------------------------------------------------------------------
// Launch
// ---------------------------------------------------------------------------
extern "C" void kernel_launch(void* const* d_in, const int* in_sizes, int n_in,
                              void* d_out, int out_size)
{
    const float* ue = nullptr; const float* ie = nullptr;
    const float* vals = nullptr; const int* rows = nullptr; const int* cols = nullptr;
    int nnz_seen = 0;
    for (int i = 0; i < n_in; i++) {
        if (in_sizes[i] == NUSERS * DIM)      ue = (const float*)d_in[i];
        else if (in_sizes[i] == NITEMS * DIM) ie = (const float*)d_in[i];
        else if (in_sizes[i] == NNZ_E) {
            if (nnz_seen == 0)      vals = (const float*)d_in[i];
            else if (nnz_seen == 1) rows = (const int*)d_in[i];
            else                    cols = (const int*)d_in[i];
            nnz_seen++;
        }
    }
    float* out = (float*)d_out;

    // JAX key derivation (validated): base=(0,42); hk=cipher(base,(0,hop));
    // ke=cipher(hk,(0,0)), km=cipher(hk,(0,1))
    uint32_t ke0[NHOPS], ke1[NHOPS], km0[NHOPS], km1[NHOPS];
    for (int h = 0; h < NHOPS; h++) {
        uint32_t h0, h1;
        threefry2x32(0u, 42u, 0u, (uint32_t)h, h0, h1);
        threefry2x32(h0, h1, 0u, 0u, ke0[h], ke1[h]);
        threefry2x32(h0, h1, 0u, 1u, km0[h], km1[h]);
    }

    const int TB = 256;
    unsigned gb_node = (NNODES + TB - 1) / TB;
    unsigned gb_edge = (NNZ_E + TB - 1) / TB;
    unsigned gb_fuse = ((unsigned)NNODES * 32u + TB - 1) / TB;  // 1 warp/row

    k_zero<<<gb_node, TB>>>();
    k_hist<<<gb_edge, TB>>>(rows);
    k_scan1<<<NBLK, TB>>>();
    k_scan2<<<1, 512>>>();
    k_scan3<<<gb_node, TB>>>();
    k_scatter<<<gb_edge, TB>>>(rows, cols, vals,
                               ke0[0], ke1[0], ke0[1], ke1[1], ke0[2], ke1[2]);

    const uint32_t one = 1u;  // opaque to the compiler (kernel argument)
    k_spmm_fused<0><<<gb_fuse, TB>>>(ue, ie, out, km0[0], km1[0], one);
    k_spmm_fused<1><<<gb_fuse, TB>>>(ue, ie, out, km0[1], km1[1], one);
    k_spmm_fused<2><<<gb_fuse, TB>>>(ue, ie, out, km0[2], km1[2], one);
}